// round 16
// baseline (speedup 1.0000x reference)
#include <cuda_runtime.h>
#include <math.h>

#define NN 100000
#define EE 1600000
#define FF 128
#define DD 64
#define GG 512
#define CC 2
#define BN_EPS 1e-5f

// ---------------- scratch (no allocs allowed; 16B-aligned for float4/red.v4) ----------------
__device__ __align__(16) float  g_u [NN * DD];      // x @ w1a (projected features)
__device__ __align__(16) float  g_za[NN * DD];      // layer0 aggregate: u + sum w*u[src]
__device__ __align__(16) float  g_h0[NN * DD];      // layer0 out -> normalized in place
__device__ __align__(16) float  g_z1[NN * DD];      // layer1 accumulator
__device__ __align__(16) float  g_h1[NN * DD];      // layer1 out (pre-BN)
__device__ __align__(16) double g_bnacc[4 * DD];    // [sum0, sq0, sum1, sq1]
__device__ __align__(16) float  g_p0[GG * DD];
__device__ __align__(16) float  g_p1[GG * DD];
__device__ int g_idx64;                             // 1 if index buffers are int64

__device__ __forceinline__ void red_add_v4(float* p, float4 v) {
    asm volatile("red.global.add.v4.f32 [%0], {%1, %2, %3, %4};"
                 :: "l"(p), "f"(v.x), "f"(v.y), "f"(v.z), "f"(v.w)
                 : "memory");
}

__device__ __forceinline__ int load_idx(const void* p, int e, int idx64) {
    return idx64 ? (int)((const long long*)p)[e] : ((const int*)p)[e];
}

// ---------------- dtype detection: int64 buffers have all-zero high words ----------------
__global__ void k_detect(const int* __restrict__ ei) {
    bool all0 = true;
    for (int i = 1; i < 256; i += 2)
        if (ei[i] != 0) { all0 = false; break; }
    g_idx64 = all0 ? 1 : 0;
}

// Pitches: activation rows padded to float4-aligned strides (LDS.128-friendly).
#define P64 68     // 64-wide tiles -> 68 floats (272B, 16B-aligned)
#define P128 132   // 128-wide tiles -> 132 floats (528B, 16B-aligned)

// GEMM inner block: 128 rows/CTA, thread = 8 rows x 4 cols, two 4-row halves.
#define GEMM_K4(acts, PITCH, wgt, K, acc)                                      \
    _Pragma("unroll 2")                                                        \
    for (int k = 0; k < K; k += 4) {                                           \
        _Pragma("unroll")                                                      \
        for (int half = 0; half < 2; half++) {                                 \
            float ya[4][4];                                                    \
            _Pragma("unroll")                                                  \
            for (int i = 0; i < 4; i++) {                                      \
                float4 t = *(const float4*)&acts[(ty + 16 * (4 * half + i)) * PITCH + k]; \
                ya[i][0] = t.x; ya[i][1] = t.y; ya[i][2] = t.z; ya[i][3] = t.w; \
            }                                                                  \
            _Pragma("unroll")                                                  \
            for (int kk = 0; kk < 4; kk++) {                                   \
                float4 w = *(const float4*)&wgt[(k + kk) * 64 + 4 * tx];       \
                _Pragma("unroll")                                              \
                for (int i = 0; i < 4; i++) {                                  \
                    acc[4 * half + i][0] = fmaf(ya[i][kk], w.x, acc[4 * half + i][0]); \
                    acc[4 * half + i][1] = fmaf(ya[i][kk], w.y, acc[4 * half + i][1]); \
                    acc[4 * half + i][2] = fmaf(ya[i][kk], w.z, acc[4 * half + i][2]); \
                    acc[4 * half + i][3] = fmaf(ya[i][kk], w.w, acc[4 * half + i][3]); \
                }                                                              \
            }                                                                  \
        }                                                                      \
    }

// ---------------- projection: u = x @ w1a (no bias; linearity lets scatter run in D=64) ----
// 128 nodes/block.
__global__ void k_proj(const float* __restrict__ x, const float* __restrict__ w1,
                       float* __restrict__ u, float* __restrict__ zagg)
{
    extern __shared__ float sm[];
    float* zs  = sm;                  // 128 x P128
    float* w1s = zs + 128 * P128;     // 128 x 64

    const int tid  = threadIdx.x;
    const int base = blockIdx.x * 128;

    for (int i = tid; i < FF * 64; i += 256) w1s[i] = w1[i];
    for (int i = tid; i < 128 * FF; i += 256) {
        int r = i >> 7, c = i & 127;
        int n = base + r;
        zs[r * P128 + c] = (n < NN) ? x[(size_t)n * FF + c] : 0.f;
    }
    __syncthreads();

    const int ty = tid >> 4, tx = tid & 15;
    float acc[8][4];
    #pragma unroll
    for (int i = 0; i < 8; i++)
        #pragma unroll
        for (int j = 0; j < 4; j++) acc[i][j] = 0.f;

    GEMM_K4(zs, P128, w1s, FF, acc)

    #pragma unroll
    for (int i = 0; i < 8; i++) {
        int n = base + ty + 16 * i;
        if (n < NN) {
            float4 v = make_float4(acc[i][0], acc[i][1], acc[i][2], acc[i][3]);
            *(float4*)&u   [(size_t)n * 64 + 4 * tx] = v;
            *(float4*)&zagg[(size_t)n * 64 + 4 * tx] = v;   // scatter accumulates on top
        }
    }
}

// ---------------- edge scatter (D=64): acc[dst] += w * h[src] ----------------
// Warp = 2 edges (16 threads each). Edge metadata loaded by ONE lane per half-warp
// and distributed via shfl: cuts 48 redundant scalar LDG issues/edge to 3 LDG + 3 SHFL/warp.
__global__ void k_scatter(const void* __restrict__ ei,
                          const float* __restrict__ ew,
                          const float* __restrict__ h,
                          float* __restrict__ acc)
{
    int t = blockIdx.x * blockDim.x + threadIdx.x;
    int e = t >> 4;
    if (e >= EE) return;
    const int idx64 = g_idx64;          // grid-uniform
    const int lane  = threadIdx.x & 31;
    const int src_lane = lane & 16;     // lane 0 / 16 own the metadata for their half-warp

    int s = 0, d = 0;
    float w = 0.f;
    if ((lane & 15) == 0) {
        s = load_idx(ei, e, idx64);
        d = load_idx(ei, EE + e, idx64);
        w = ew[e];
    }
    s = __shfl_sync(0xffffffffu, s, src_lane);
    d = __shfl_sync(0xffffffffu, d, src_lane);
    w = __shfl_sync(0xffffffffu, w, src_lane);

    int c = (t & 15) * 4;
    float4 v = *(const float4*)(h + (size_t)s * 64 + c);
    float4 m = make_float4(v.x * w, v.y * w, v.z * w, v.w * w);
    red_add_v4(acc + (size_t)d * 64 + c, m);
}

// ---------------- layer0 tail: h = relu(relu(z+b1)@w2+b2), + BN partial sums ----------------
// 128 nodes/block.
__global__ void k_mlp2(const float* __restrict__ zin,
                       const float* __restrict__ b1, const float* __restrict__ w2,
                       const float* __restrict__ b2,
                       float* __restrict__ hout, double* __restrict__ bnacc)
{
    extern __shared__ float sm[];
    float* ys   = sm;                 // 128 x P64
    float* w2s  = ys + 128 * P64;     // 64 x 64
    float* bsum = w2s + 64 * 64;      // 64
    float* bsq  = bsum + 64;          // 64

    const int tid  = threadIdx.x;
    const int base = blockIdx.x * 128;

    for (int i = tid; i < 64 * 64; i += 256) w2s[i] = w2[i];
    if (tid < 64) { bsum[tid] = 0.f; bsq[tid] = 0.f; }
    for (int i = tid; i < 128 * 64; i += 256) {
        int r = i >> 6, c = i & 63;
        int n = base + r;
        ys[r * P64 + c] = (n < NN) ? fmaxf(zin[(size_t)n * 64 + c] + __ldg(&b1[c]), 0.f) : 0.f;
    }
    __syncthreads();

    const int ty = tid >> 4, tx = tid & 15;
    float acc[8][4];
    #pragma unroll
    for (int i = 0; i < 8; i++)
        #pragma unroll
        for (int j = 0; j < 4; j++) acc[i][j] = __ldg(&b2[4 * tx + j]);

    GEMM_K4(ys, P64, w2s, 64, acc)

    float ls[4] = {0.f, 0.f, 0.f, 0.f}, lq[4] = {0.f, 0.f, 0.f, 0.f};
    #pragma unroll
    for (int i = 0; i < 8; i++) {
        int n = base + ty + 16 * i;
        if (n < NN) {
            float4 v;
            v.x = fmaxf(acc[i][0], 0.f);
            v.y = fmaxf(acc[i][1], 0.f);
            v.z = fmaxf(acc[i][2], 0.f);
            v.w = fmaxf(acc[i][3], 0.f);
            *(float4*)&hout[(size_t)n * 64 + 4 * tx] = v;
            ls[0] += v.x; lq[0] += v.x * v.x;
            ls[1] += v.y; lq[1] += v.y * v.y;
            ls[2] += v.z; lq[2] += v.z * v.z;
            ls[3] += v.w; lq[3] += v.w * v.w;
        }
    }
    #pragma unroll
    for (int j = 0; j < 4; j++) {
        atomicAdd(&bsum[4 * tx + j], ls[j]);
        atomicAdd(&bsq [4 * tx + j], lq[j]);
    }
    __syncthreads();
    if (tid < 64) {
        atomicAdd(&bnacc[tid],      (double)bsum[tid]);
        atomicAdd(&bnacc[64 + tid], (double)bsq[tid]);
    }
}

// ---------------- full fused MLP (layer 1): out = relu(relu(z@w1+b1)@w2+b2) + BN sums -------
// 128 nodes/block.
__global__ void k_mlp(const float* __restrict__ zin,
                      const float* __restrict__ w1, const float* __restrict__ b1,
                      const float* __restrict__ w2, const float* __restrict__ b2,
                      float* __restrict__ hout, double* __restrict__ bnacc)
{
    extern __shared__ float sm[];
    float* zs   = sm;                         // 128 x P64
    float* w1s  = zs + 128 * P64;             // 64 x 64
    float* w2s  = w1s + 64 * 64;              // 64 x 64
    float* ys   = w2s + 64 * 64;              // 128 x P64
    float* bsum = ys + 128 * P64;             // 64
    float* bsq  = bsum + 64;                  // 64

    const int tid  = threadIdx.x;
    const int base = blockIdx.x * 128;

    for (int i = tid; i < 64 * 64; i += 256) { w1s[i] = w1[i]; w2s[i] = w2[i]; }
    if (tid < 64) { bsum[tid] = 0.f; bsq[tid] = 0.f; }
    for (int i = tid; i < 128 * 64; i += 256) {
        int r = i >> 6, c = i & 63;
        int n = base + r;
        zs[r * P64 + c] = (n < NN) ? zin[(size_t)n * 64 + c] : 0.f;
    }
    __syncthreads();

    const int ty = tid >> 4, tx = tid & 15;

    float acc[8][4];
    #pragma unroll
    for (int i = 0; i < 8; i++)
        #pragma unroll
        for (int j = 0; j < 4; j++) acc[i][j] = __ldg(&b1[4 * tx + j]);

    GEMM_K4(zs, P64, w1s, 64, acc)

    #pragma unroll
    for (int i = 0; i < 8; i++)
        #pragma unroll
        for (int j = 0; j < 4; j++)
            ys[(ty + 16 * i) * P64 + 4 * tx + j] = fmaxf(acc[i][j], 0.f);
    __syncthreads();

    float o[8][4];
    #pragma unroll
    for (int i = 0; i < 8; i++)
        #pragma unroll
        for (int j = 0; j < 4; j++) o[i][j] = __ldg(&b2[4 * tx + j]);

    GEMM_K4(ys, P64, w2s, 64, o)

    float ls[4] = {0.f, 0.f, 0.f, 0.f}, lq[4] = {0.f, 0.f, 0.f, 0.f};
    #pragma unroll
    for (int i = 0; i < 8; i++) {
        int n = base + ty + 16 * i;
        if (n < NN) {
            float4 v;
            v.x = fmaxf(o[i][0], 0.f);
            v.y = fmaxf(o[i][1], 0.f);
            v.z = fmaxf(o[i][2], 0.f);
            v.w = fmaxf(o[i][3], 0.f);
            *(float4*)&hout[(size_t)n * 64 + 4 * tx] = v;
            ls[0] += v.x; lq[0] += v.x * v.x;
            ls[1] += v.y; lq[1] += v.y * v.y;
            ls[2] += v.z; lq[2] += v.z * v.z;
            ls[3] += v.w; lq[3] += v.w * v.w;
        }
    }
    #pragma unroll
    for (int j = 0; j < 4; j++) {
        atomicAdd(&bsum[4 * tx + j], ls[j]);
        atomicAdd(&bsq [4 * tx + j], lq[j]);
    }
    __syncthreads();
    if (tid < 64) {
        atomicAdd(&bnacc[tid],      (double)bsum[tid]);
        atomicAdd(&bnacc[64 + tid], (double)bsq[tid]);
    }
}

// ---------------- BN apply + pool (+ copy for next layer); scale/shift from bnacc ----------
template<bool WRITE_NEXT>
__global__ void k_bnapply(float* __restrict__ h, const double* __restrict__ bnacc,
                          const float* __restrict__ gamma, const float* __restrict__ beta,
                          const void* __restrict__ batch,
                          float* __restrict__ znext, float* __restrict__ pool)
{
    __shared__ float sscale[64], sshift[64];
    int tid = threadIdx.x;
    if (tid < 64) {
        double mean = bnacc[tid] / (double)NN;
        double var  = bnacc[64 + tid] / (double)NN - mean * mean;
        double sc   = (double)gamma[tid] / sqrt(var + (double)BN_EPS);
        sscale[tid] = (float)sc;
        sshift[tid] = (float)((double)beta[tid] - mean * sc);
    }
    __syncthreads();

    int t = blockIdx.x * blockDim.x + tid;
    if (t >= NN * 16) return;
    int n = t >> 4;
    int c = (t & 15) * 4;
    float4 v  = *(const float4*)&h[(size_t)n * 64 + c];
    float4 sc = *(const float4*)&sscale[c];
    float4 sh = *(const float4*)&sshift[c];
    v.x = fmaf(v.x, sc.x, sh.x);
    v.y = fmaf(v.y, sc.y, sh.y);
    v.z = fmaf(v.z, sc.z, sh.z);
    v.w = fmaf(v.w, sc.w, sh.w);
    if (WRITE_NEXT) {
        *(float4*)&h[(size_t)n * 64 + c] = v;       // normalized h needed by layer-1 gather
        *(float4*)&znext[(size_t)n * 64 + c] = v;   // accumulator init (z = h + agg)
    }
    int b = load_idx(batch, n, g_idx64);             // broadcast in warp
    red_add_v4(&pool[(size_t)b * 64 + c], v);
}

// ---------------- classifier head + log_softmax ----------------
__global__ void k_head(const float* __restrict__ p0, const float* __restrict__ p1,
                       const float* __restrict__ wf,  const float* __restrict__ bfv,
                       const float* __restrict__ wf1, const float* __restrict__ bf1,
                       const float* __restrict__ wf2, const float* __restrict__ bf2,
                       float* __restrict__ out)
{
    extern __shared__ float sm[];
    float* gs  = sm;                 // 64 x P128
    float* wfs = gs + 64 * P128;     // 128 x 64
    float* w1s = wfs + 128 * 64;     // 64 x 64
    float* ys  = w1s + 64 * 64;      // 64 x P64
    float* y2  = ys + 64 * P64;      // 64 x P64
    float* bfs = y2 + 64 * P64;      // 64
    float* b1s = bfs + 64;           // 64
    float* w2s = b1s + 64;           // 128
    float* b2s = w2s + 128;          // 2

    const int tid = threadIdx.x;
    const int gb  = blockIdx.x * 64;

    for (int i = tid; i < 128 * 64; i += 256) wfs[i] = wf[i];
    for (int i = tid; i < 64 * 64;  i += 256) w1s[i] = wf1[i];
    if (tid < 128) w2s[tid] = wf2[tid];
    if (tid < 64)  { bfs[tid] = bfv[tid]; b1s[tid] = bf1[tid]; }
    if (tid < 2)   b2s[tid] = bf2[tid];
    for (int i = tid; i < 64 * 128; i += 256) {
        int r = i >> 7, c = i & 127;
        gs[r * P128 + c] = (c < 64) ? p0[(size_t)(gb + r) * 64 + c]
                                    : p1[(size_t)(gb + r) * 64 + (c - 64)];
    }
    __syncthreads();

    const int ty = tid >> 4, tx = tid & 15;
    float acc[4][4];
    #pragma unroll
    for (int i = 0; i < 4; i++)
        #pragma unroll
        for (int j = 0; j < 4; j++) acc[i][j] = bfs[4 * tx + j];
    #pragma unroll 4
    for (int k = 0; k < 128; k += 4) {
        float ya[4][4];
        #pragma unroll
        for (int i = 0; i < 4; i++) {
            float4 t = *(const float4*)&gs[(ty + 16 * i) * P128 + k];
            ya[i][0] = t.x; ya[i][1] = t.y; ya[i][2] = t.z; ya[i][3] = t.w;
        }
        #pragma unroll
        for (int kk = 0; kk < 4; kk++) {
            float4 w = *(const float4*)&wfs[(k + kk) * 64 + 4 * tx];
            #pragma unroll
            for (int i = 0; i < 4; i++) {
                acc[i][0] = fmaf(ya[i][kk], w.x, acc[i][0]);
                acc[i][1] = fmaf(ya[i][kk], w.y, acc[i][1]);
                acc[i][2] = fmaf(ya[i][kk], w.z, acc[i][2]);
                acc[i][3] = fmaf(ya[i][kk], w.w, acc[i][3]);
            }
        }
    }
    #pragma unroll
    for (int i = 0; i < 4; i++)
        #pragma unroll
        for (int j = 0; j < 4; j++)
            ys[(ty + 16 * i) * P64 + 4 * tx + j] = fmaxf(acc[i][j], 0.f);
    __syncthreads();

    float o[4][4];
    #pragma unroll
    for (int i = 0; i < 4; i++)
        #pragma unroll
        for (int j = 0; j < 4; j++) o[i][j] = b1s[4 * tx + j];
    #pragma unroll 4
    for (int k = 0; k < 64; k += 4) {
        float ya[4][4];
        #pragma unroll
        for (int i = 0; i < 4; i++) {
            float4 t = *(const float4*)&ys[(ty + 16 * i) * P64 + k];
            ya[i][0] = t.x; ya[i][1] = t.y; ya[i][2] = t.z; ya[i][3] = t.w;
        }
        #pragma unroll
        for (int kk = 0; kk < 4; kk++) {
            float4 w = *(const float4*)&w1s[(k + kk) * 64 + 4 * tx];
            #pragma unroll
            for (int i = 0; i < 4; i++) {
                o[i][0] = fmaf(ya[i][kk], w.x, o[i][0]);
                o[i][1] = fmaf(ya[i][kk], w.y, o[i][1]);
                o[i][2] = fmaf(ya[i][kk], w.z, o[i][2]);
                o[i][3] = fmaf(ya[i][kk], w.w, o[i][3]);
            }
        }
    }
    #pragma unroll
    for (int i = 0; i < 4; i++)
        #pragma unroll
        for (int j = 0; j < 4; j++)
            y2[(ty + 16 * i) * P64 + 4 * tx + j] = fmaxf(o[i][j], 0.f);
    __syncthreads();

    if (tid < 64) {
        int g = gb + tid;
        float l0 = b2s[0], l1 = b2s[1];
        #pragma unroll 4
        for (int k = 0; k < 64; ++k) {
            float yv = y2[tid * P64 + k];
            l0 = fmaf(yv, w2s[k * 2 + 0], l0);
            l1 = fmaf(yv, w2s[k * 2 + 1], l1);
        }
        float m = fmaxf(l0, l1);
        float lse = m + logf(expf(l0 - m) + expf(l1 - m));
        out[g * 2 + 0] = l0 - lse;
        out[g * 2 + 1] = l1 - lse;
    }
}

// ---------------- launch ----------------
extern "C" void kernel_launch(void* const* d_in, const int* in_sizes, int n_in,
                              void* d_out, int out_size)
{
    const float* x     = (const float*)d_in[0];
    const void*  ei    = d_in[1];                  // int32 or int64, detected on device
    const float* ew    = (const float*)d_in[2];
    const void*  batch = d_in[3];                  // same dtype as ei
    const float *w1a = (const float*)d_in[4],  *b1a = (const float*)d_in[5];
    const float *w2a = (const float*)d_in[6],  *b2a = (const float*)d_in[7];
    const float *ga0 = (const float*)d_in[8],  *be0 = (const float*)d_in[9];
    const float *w1b = (const float*)d_in[10], *b1b = (const float*)d_in[11];
    const float *w2b = (const float*)d_in[12], *b2b = (const float*)d_in[13];
    const float *ga1 = (const float*)d_in[14], *be1 = (const float*)d_in[15];
    const float *wf  = (const float*)d_in[16], *bfv = (const float*)d_in[17];
    const float *wf1 = (const float*)d_in[18], *bf1 = (const float*)d_in[19];
    const float *wf2 = (const float*)d_in[20], *bf2 = (const float*)d_in[21];
    float* out = (float*)d_out;

    float *u, *za, *h0, *z1, *h1, *p0, *p1;
    double* bnacc;
    cudaGetSymbolAddress((void**)&u,  g_u);
    cudaGetSymbolAddress((void**)&za, g_za);
    cudaGetSymbolAddress((void**)&h0, g_h0);
    cudaGetSymbolAddress((void**)&z1, g_z1);
    cudaGetSymbolAddress((void**)&h1, g_h1);
    cudaGetSymbolAddress((void**)&p0, g_p0);
    cudaGetSymbolAddress((void**)&p1, g_p1);
    cudaGetSymbolAddress((void**)&bnacc, g_bnacc);

    const int SMEM_PROJ = (128 * P128 + 128 * 64) * 4;
    const int SMEM_MLP2 = (128 * P64 + 64 * 64 + 2 * 64) * 4;
    const int SMEM_MLP  = (2 * 128 * P64 + 2 * 64 * 64 + 2 * 64) * 4;
    const int SMEM_HEAD = (64 * P128 + 128 * 64 + 64 * 64 + 2 * 64 * P64 + 2 * 64 + 128 + 4) * 4;
    cudaFuncSetAttribute((void*)k_proj, cudaFuncAttributeMaxDynamicSharedMemorySize, SMEM_PROJ);
    cudaFuncSetAttribute((void*)k_mlp2, cudaFuncAttributeMaxDynamicSharedMemorySize, SMEM_MLP2);
    cudaFuncSetAttribute((void*)k_mlp,  cudaFuncAttributeMaxDynamicSharedMemorySize, SMEM_MLP);
    cudaFuncSetAttribute((void*)k_head, cudaFuncAttributeMaxDynamicSharedMemorySize, SMEM_HEAD);

    // dtype detection must precede any index consumer
    k_detect<<<1, 1>>>((const int*)ei);

    cudaMemsetAsync(bnacc, 0, sizeof(double) * 4 * DD, 0);
    cudaMemsetAsync(p0, 0, sizeof(float) * GG * DD, 0);
    cudaMemsetAsync(p1, 0, sizeof(float) * GG * DD, 0);

    const int NBLK128 = (NN + 127) / 128;
    const int SBLK    = (EE * 16 + 255) / 256;
    const int ABLK    = (NN * 16 + 255) / 256;

    // layer 0: project first (linearity), scatter in D=64 domain
    k_proj<<<NBLK128, 256, SMEM_PROJ>>>(x, w1a, u, za);
    k_scatter<<<SBLK, 256>>>(ei, ew, u, za);
    k_mlp2<<<NBLK128, 256, SMEM_MLP2>>>(za, b1a, w2a, b2a, h0, bnacc);
    k_bnapply<true><<<ABLK, 256>>>(h0, bnacc, ga0, be0, batch, z1, p0);

    // layer 1
    k_scatter<<<SBLK, 256>>>(ei, ew, h0, z1);
    k_mlp<<<NBLK128, 256, SMEM_MLP>>>(z1, w1b, b1b, w2b, b2b, h1, bnacc + 2 * DD);
    k_bnapply<false><<<ABLK, 256>>>(h1, bnacc + 2 * DD, ga1, be1, batch, nullptr, p1);

    // head
    k_head<<<GG / 64, 256, SMEM_HEAD>>>(p0, p1, wf, bfv, wf1, bf1, wf2, bf2, out);
}

// round 17
// speedup vs baseline: 1.0455x; 1.0455x over previous
#include <cuda_runtime.h>
#include <math.h>

#define NN 100000
#define EE 1600000
#define FF 128
#define DD 64
#define GG 512
#define CC 2
#define BN_EPS 1e-5f

// ---------------- scratch (no allocs allowed; 16B-aligned for float4/red.v4) ----------------
__device__ __align__(16) float  g_u [NN * DD];      // x @ w1a (projected features)
__device__ __align__(16) float  g_za[NN * DD];      // layer0 aggregate: u + sum w*u[src]
__device__ __align__(16) float  g_h0[NN * DD];      // layer0 out -> normalized in place
__device__ __align__(16) float  g_z1[NN * DD];      // layer1 accumulator
__device__ __align__(16) float  g_h1[NN * DD];      // layer1 out (pre-BN)
__device__ __align__(16) double g_bnacc[4 * DD];    // [sum0, sq0, sum1, sq1]
__device__ __align__(16) float  g_p0[GG * DD];
__device__ __align__(16) float  g_p1[GG * DD];
__device__ int g_idx64;                             // 1 if index buffers are int64

__device__ __forceinline__ void red_add_v4(float* p, float4 v) {
    asm volatile("red.global.add.v4.f32 [%0], {%1, %2, %3, %4};"
                 :: "l"(p), "f"(v.x), "f"(v.y), "f"(v.z), "f"(v.w)
                 : "memory");
}

__device__ __forceinline__ int load_idx(const void* p, int e, int idx64) {
    return idx64 ? (int)((const long long*)p)[e] : ((const int*)p)[e];
}

// ---------------- dtype detection: int64 buffers have all-zero high words ----------------
__global__ void k_detect(const int* __restrict__ ei) {
    bool all0 = true;
    for (int i = 1; i < 256; i += 2)
        if (ei[i] != 0) { all0 = false; break; }
    g_idx64 = all0 ? 1 : 0;
}

// Pitches: activation rows padded to float4-aligned strides (LDS.128-friendly).
#define P64 68     // 64-wide tiles -> 68 floats (272B, 16B-aligned)
#define P128 132   // 128-wide tiles -> 132 floats (528B, 16B-aligned)

// GEMM inner block: 128 rows/CTA, thread = 8 rows x 4 cols, two 4-row halves.
#define GEMM_K4(acts, PITCH, wgt, K, acc)                                      \
    _Pragma("unroll 2")                                                        \
    for (int k = 0; k < K; k += 4) {                                           \
        _Pragma("unroll")                                                      \
        for (int half = 0; half < 2; half++) {                                 \
            float ya[4][4];                                                    \
            _Pragma("unroll")                                                  \
            for (int i = 0; i < 4; i++) {                                      \
                float4 t = *(const float4*)&acts[(ty + 16 * (4 * half + i)) * PITCH + k]; \
                ya[i][0] = t.x; ya[i][1] = t.y; ya[i][2] = t.z; ya[i][3] = t.w; \
            }                                                                  \
            _Pragma("unroll")                                                  \
            for (int kk = 0; kk < 4; kk++) {                                   \
                float4 w = *(const float4*)&wgt[(k + kk) * 64 + 4 * tx];       \
                _Pragma("unroll")                                              \
                for (int i = 0; i < 4; i++) {                                  \
                    acc[4 * half + i][0] = fmaf(ya[i][kk], w.x, acc[4 * half + i][0]); \
                    acc[4 * half + i][1] = fmaf(ya[i][kk], w.y, acc[4 * half + i][1]); \
                    acc[4 * half + i][2] = fmaf(ya[i][kk], w.z, acc[4 * half + i][2]); \
                    acc[4 * half + i][3] = fmaf(ya[i][kk], w.w, acc[4 * half + i][3]); \
                }                                                              \
            }                                                                  \
        }                                                                      \
    }

// ---------------- projection: u = x @ w1a (no bias; linearity lets scatter run in D=64) ----
// 128 nodes/block.
__global__ void k_proj(const float* __restrict__ x, const float* __restrict__ w1,
                       float* __restrict__ u, float* __restrict__ zagg)
{
    extern __shared__ float sm[];
    float* zs  = sm;                  // 128 x P128
    float* w1s = zs + 128 * P128;     // 128 x 64

    const int tid  = threadIdx.x;
    const int base = blockIdx.x * 128;

    for (int i = tid; i < FF * 64; i += 256) w1s[i] = w1[i];
    for (int i = tid; i < 128 * FF; i += 256) {
        int r = i >> 7, c = i & 127;
        int n = base + r;
        zs[r * P128 + c] = (n < NN) ? x[(size_t)n * FF + c] : 0.f;
    }
    __syncthreads();

    const int ty = tid >> 4, tx = tid & 15;
    float acc[8][4];
    #pragma unroll
    for (int i = 0; i < 8; i++)
        #pragma unroll
        for (int j = 0; j < 4; j++) acc[i][j] = 0.f;

    GEMM_K4(zs, P128, w1s, FF, acc)

    #pragma unroll
    for (int i = 0; i < 8; i++) {
        int n = base + ty + 16 * i;
        if (n < NN) {
            float4 v = make_float4(acc[i][0], acc[i][1], acc[i][2], acc[i][3]);
            *(float4*)&u   [(size_t)n * 64 + 4 * tx] = v;
            *(float4*)&zagg[(size_t)n * 64 + 4 * tx] = v;   // scatter accumulates on top
        }
    }
}

// ---------------- edge scatter (D=64): acc[dst] += w * h[src] ----------------
// R13-measured form: metadata loads are warp-uniform -> single LDG issue + HW broadcast.
__global__ void k_scatter(const void* __restrict__ ei,
                          const float* __restrict__ ew,
                          const float* __restrict__ h,
                          float* __restrict__ acc)
{
    int t = blockIdx.x * blockDim.x + threadIdx.x;
    int e = t >> 4;
    if (e >= EE) return;
    const int idx64 = g_idx64;          // grid-uniform
    int c = (t & 15) * 4;
    int s = load_idx(ei, e, idx64);     // broadcast within half-warp
    int d = load_idx(ei, EE + e, idx64);
    float w = ew[e];
    float4 v = *(const float4*)(h + (size_t)s * 64 + c);
    float4 m = make_float4(v.x * w, v.y * w, v.z * w, v.w * w);
    red_add_v4(acc + (size_t)d * 64 + c, m);
}

// ---------------- layer0 tail: h = relu(relu(z+b1)@w2+b2), + BN partial sums ----------------
// 128 nodes/block.
__global__ void k_mlp2(const float* __restrict__ zin,
                       const float* __restrict__ b1, const float* __restrict__ w2,
                       const float* __restrict__ b2,
                       float* __restrict__ hout, double* __restrict__ bnacc)
{
    extern __shared__ float sm[];
    float* ys   = sm;                 // 128 x P64
    float* w2s  = ys + 128 * P64;     // 64 x 64
    float* bsum = w2s + 64 * 64;      // 64
    float* bsq  = bsum + 64;          // 64

    const int tid  = threadIdx.x;
    const int base = blockIdx.x * 128;

    for (int i = tid; i < 64 * 64; i += 256) w2s[i] = w2[i];
    if (tid < 64) { bsum[tid] = 0.f; bsq[tid] = 0.f; }
    for (int i = tid; i < 128 * 64; i += 256) {
        int r = i >> 6, c = i & 63;
        int n = base + r;
        ys[r * P64 + c] = (n < NN) ? fmaxf(zin[(size_t)n * 64 + c] + __ldg(&b1[c]), 0.f) : 0.f;
    }
    __syncthreads();

    const int ty = tid >> 4, tx = tid & 15;
    float acc[8][4];
    #pragma unroll
    for (int i = 0; i < 8; i++)
        #pragma unroll
        for (int j = 0; j < 4; j++) acc[i][j] = __ldg(&b2[4 * tx + j]);

    GEMM_K4(ys, P64, w2s, 64, acc)

    float ls[4] = {0.f, 0.f, 0.f, 0.f}, lq[4] = {0.f, 0.f, 0.f, 0.f};
    #pragma unroll
    for (int i = 0; i < 8; i++) {
        int n = base + ty + 16 * i;
        if (n < NN) {
            float4 v;
            v.x = fmaxf(acc[i][0], 0.f);
            v.y = fmaxf(acc[i][1], 0.f);
            v.z = fmaxf(acc[i][2], 0.f);
            v.w = fmaxf(acc[i][3], 0.f);
            *(float4*)&hout[(size_t)n * 64 + 4 * tx] = v;
            ls[0] += v.x; lq[0] += v.x * v.x;
            ls[1] += v.y; lq[1] += v.y * v.y;
            ls[2] += v.z; lq[2] += v.z * v.z;
            ls[3] += v.w; lq[3] += v.w * v.w;
        }
    }
    #pragma unroll
    for (int j = 0; j < 4; j++) {
        atomicAdd(&bsum[4 * tx + j], ls[j]);
        atomicAdd(&bsq [4 * tx + j], lq[j]);
    }
    __syncthreads();
    if (tid < 64) {
        atomicAdd(&bnacc[tid],      (double)bsum[tid]);
        atomicAdd(&bnacc[64 + tid], (double)bsq[tid]);
    }
}

// ---------------- full fused MLP (layer 1): out = relu(relu(z@w1+b1)@w2+b2) + BN sums -------
// 128 nodes/block; zs tile REUSED for ys (phase A fully consumes zs before barrier)
// -> smem ~68KB -> 3 CTAs/SM instead of 2.
__global__ void k_mlp(const float* __restrict__ zin,
                      const float* __restrict__ w1, const float* __restrict__ b1,
                      const float* __restrict__ w2, const float* __restrict__ b2,
                      float* __restrict__ hout, double* __restrict__ bnacc)
{
    extern __shared__ float sm[];
    float* zs   = sm;                         // 128 x P64  (reused as ys)
    float* w1s  = zs + 128 * P64;             // 64 x 64
    float* w2s  = w1s + 64 * 64;              // 64 x 64
    float* bsum = w2s + 64 * 64;              // 64
    float* bsq  = bsum + 64;                  // 64

    const int tid  = threadIdx.x;
    const int base = blockIdx.x * 128;

    for (int i = tid; i < 64 * 64; i += 256) { w1s[i] = w1[i]; w2s[i] = w2[i]; }
    if (tid < 64) { bsum[tid] = 0.f; bsq[tid] = 0.f; }
    for (int i = tid; i < 128 * 64; i += 256) {
        int r = i >> 6, c = i & 63;
        int n = base + r;
        zs[r * P64 + c] = (n < NN) ? zin[(size_t)n * 64 + c] : 0.f;
    }
    __syncthreads();

    const int ty = tid >> 4, tx = tid & 15;

    float acc[8][4];
    #pragma unroll
    for (int i = 0; i < 8; i++)
        #pragma unroll
        for (int j = 0; j < 4; j++) acc[i][j] = __ldg(&b1[4 * tx + j]);

    GEMM_K4(zs, P64, w1s, 64, acc)

    __syncthreads();   // all phase-A reads of zs complete before overwrite
    #pragma unroll
    for (int i = 0; i < 8; i++)
        #pragma unroll
        for (int j = 0; j < 4; j++)
            zs[(ty + 16 * i) * P64 + 4 * tx + j] = fmaxf(acc[i][j], 0.f);
    __syncthreads();

    float o[8][4];
    #pragma unroll
    for (int i = 0; i < 8; i++)
        #pragma unroll
        for (int j = 0; j < 4; j++) o[i][j] = __ldg(&b2[4 * tx + j]);

    GEMM_K4(zs, P64, w2s, 64, o)

    float ls[4] = {0.f, 0.f, 0.f, 0.f}, lq[4] = {0.f, 0.f, 0.f, 0.f};
    #pragma unroll
    for (int i = 0; i < 8; i++) {
        int n = base + ty + 16 * i;
        if (n < NN) {
            float4 v;
            v.x = fmaxf(o[i][0], 0.f);
            v.y = fmaxf(o[i][1], 0.f);
            v.z = fmaxf(o[i][2], 0.f);
            v.w = fmaxf(o[i][3], 0.f);
            *(float4*)&hout[(size_t)n * 64 + 4 * tx] = v;
            ls[0] += v.x; lq[0] += v.x * v.x;
            ls[1] += v.y; lq[1] += v.y * v.y;
            ls[2] += v.z; lq[2] += v.z * v.z;
            ls[3] += v.w; lq[3] += v.w * v.w;
        }
    }
    #pragma unroll
    for (int j = 0; j < 4; j++) {
        atomicAdd(&bsum[4 * tx + j], ls[j]);
        atomicAdd(&bsq [4 * tx + j], lq[j]);
    }
    __syncthreads();
    if (tid < 64) {
        atomicAdd(&bnacc[tid],      (double)bsum[tid]);
        atomicAdd(&bnacc[64 + tid], (double)bsq[tid]);
    }
}

// ---------------- BN apply + pool (+ copy for next layer); scale/shift from bnacc ----------
template<bool WRITE_NEXT>
__global__ void k_bnapply(float* __restrict__ h, const double* __restrict__ bnacc,
                          const float* __restrict__ gamma, const float* __restrict__ beta,
                          const void* __restrict__ batch,
                          float* __restrict__ znext, float* __restrict__ pool)
{
    __shared__ float sscale[64], sshift[64];
    int tid = threadIdx.x;
    if (tid < 64) {
        double mean = bnacc[tid] / (double)NN;
        double var  = bnacc[64 + tid] / (double)NN - mean * mean;
        double sc   = (double)gamma[tid] / sqrt(var + (double)BN_EPS);
        sscale[tid] = (float)sc;
        sshift[tid] = (float)((double)beta[tid] - mean * sc);
    }
    __syncthreads();

    int t = blockIdx.x * blockDim.x + tid;
    if (t >= NN * 16) return;
    int n = t >> 4;
    int c = (t & 15) * 4;
    float4 v  = *(const float4*)&h[(size_t)n * 64 + c];
    float4 sc = *(const float4*)&sscale[c];
    float4 sh = *(const float4*)&sshift[c];
    v.x = fmaf(v.x, sc.x, sh.x);
    v.y = fmaf(v.y, sc.y, sh.y);
    v.z = fmaf(v.z, sc.z, sh.z);
    v.w = fmaf(v.w, sc.w, sh.w);
    if (WRITE_NEXT) {
        *(float4*)&h[(size_t)n * 64 + c] = v;       // normalized h needed by layer-1 gather
        *(float4*)&znext[(size_t)n * 64 + c] = v;   // accumulator init (z = h + agg)
    }
    int b = load_idx(batch, n, g_idx64);             // broadcast in warp
    red_add_v4(&pool[(size_t)b * 64 + c], v);
}

// ---------------- classifier head + log_softmax ----------------
__global__ void k_head(const float* __restrict__ p0, const float* __restrict__ p1,
                       const float* __restrict__ wf,  const float* __restrict__ bfv,
                       const float* __restrict__ wf1, const float* __restrict__ bf1,
                       const float* __restrict__ wf2, const float* __restrict__ bf2,
                       float* __restrict__ out)
{
    extern __shared__ float sm[];
    float* gs  = sm;                 // 64 x P128
    float* wfs = gs + 64 * P128;     // 128 x 64
    float* w1s = wfs + 128 * 64;     // 64 x 64
    float* ys  = w1s + 64 * 64;      // 64 x P64
    float* y2  = ys + 64 * P64;      // 64 x P64
    float* bfs = y2 + 64 * P64;      // 64
    float* b1s = bfs + 64;           // 64
    float* w2s = b1s + 64;           // 128
    float* b2s = w2s + 128;          // 2

    const int tid = threadIdx.x;
    const int gb  = blockIdx.x * 64;

    for (int i = tid; i < 128 * 64; i += 256) wfs[i] = wf[i];
    for (int i = tid; i < 64 * 64;  i += 256) w1s[i] = wf1[i];
    if (tid < 128) w2s[tid] = wf2[tid];
    if (tid < 64)  { bfs[tid] = bfv[tid]; b1s[tid] = bf1[tid]; }
    if (tid < 2)   b2s[tid] = bf2[tid];
    for (int i = tid; i < 64 * 128; i += 256) {
        int r = i >> 7, c = i & 127;
        gs[r * P128 + c] = (c < 64) ? p0[(size_t)(gb + r) * 64 + c]
                                    : p1[(size_t)(gb + r) * 64 + (c - 64)];
    }
    __syncthreads();

    const int ty = tid >> 4, tx = tid & 15;
    float acc[4][4];
    #pragma unroll
    for (int i = 0; i < 4; i++)
        #pragma unroll
        for (int j = 0; j < 4; j++) acc[i][j] = bfs[4 * tx + j];
    #pragma unroll 4
    for (int k = 0; k < 128; k += 4) {
        float ya[4][4];
        #pragma unroll
        for (int i = 0; i < 4; i++) {
            float4 t = *(const float4*)&gs[(ty + 16 * i) * P128 + k];
            ya[i][0] = t.x; ya[i][1] = t.y; ya[i][2] = t.z; ya[i][3] = t.w;
        }
        #pragma unroll
        for (int kk = 0; kk < 4; kk++) {
            float4 w = *(const float4*)&wfs[(k + kk) * 64 + 4 * tx];
            #pragma unroll
            for (int i = 0; i < 4; i++) {
                acc[i][0] = fmaf(ya[i][kk], w.x, acc[i][0]);
                acc[i][1] = fmaf(ya[i][kk], w.y, acc[i][1]);
                acc[i][2] = fmaf(ya[i][kk], w.z, acc[i][2]);
                acc[i][3] = fmaf(ya[i][kk], w.w, acc[i][3]);
            }
        }
    }
    #pragma unroll
    for (int i = 0; i < 4; i++)
        #pragma unroll
        for (int j = 0; j < 4; j++)
            ys[(ty + 16 * i) * P64 + 4 * tx + j] = fmaxf(acc[i][j], 0.f);
    __syncthreads();

    float o[4][4];
    #pragma unroll
    for (int i = 0; i < 4; i++)
        #pragma unroll
        for (int j = 0; j < 4; j++) o[i][j] = b1s[4 * tx + j];
    #pragma unroll 4
    for (int k = 0; k < 64; k += 4) {
        float ya[4][4];
        #pragma unroll
        for (int i = 0; i < 4; i++) {
            float4 t = *(const float4*)&ys[(ty + 16 * i) * P64 + k];
            ya[i][0] = t.x; ya[i][1] = t.y; ya[i][2] = t.z; ya[i][3] = t.w;
        }
        #pragma unroll
        for (int kk = 0; kk < 4; kk++) {
            float4 w = *(const float4*)&w1s[(k + kk) * 64 + 4 * tx];
            #pragma unroll
            for (int i = 0; i < 4; i++) {
                o[i][0] = fmaf(ya[i][kk], w.x, o[i][0]);
                o[i][1] = fmaf(ya[i][kk], w.y, o[i][1]);
                o[i][2] = fmaf(ya[i][kk], w.z, o[i][2]);
                o[i][3] = fmaf(ya[i][kk], w.w, o[i][3]);
            }
        }
    }
    #pragma unroll
    for (int i = 0; i < 4; i++)
        #pragma unroll
        for (int j = 0; j < 4; j++)
            y2[(ty + 16 * i) * P64 + 4 * tx + j] = fmaxf(o[i][j], 0.f);
    __syncthreads();

    if (tid < 64) {
        int g = gb + tid;
        float l0 = b2s[0], l1 = b2s[1];
        #pragma unroll 4
        for (int k = 0; k < 64; ++k) {
            float yv = y2[tid * P64 + k];
            l0 = fmaf(yv, w2s[k * 2 + 0], l0);
            l1 = fmaf(yv, w2s[k * 2 + 1], l1);
        }
        float m = fmaxf(l0, l1);
        float lse = m + logf(expf(l0 - m) + expf(l1 - m));
        out[g * 2 + 0] = l0 - lse;
        out[g * 2 + 1] = l1 - lse;
    }
}

// ---------------- launch ----------------
extern "C" void kernel_launch(void* const* d_in, const int* in_sizes, int n_in,
                              void* d_out, int out_size)
{
    const float* x     = (const float*)d_in[0];
    const void*  ei    = d_in[1];                  // int32 or int64, detected on device
    const float* ew    = (const float*)d_in[2];
    const void*  batch = d_in[3];                  // same dtype as ei
    const float *w1a = (const float*)d_in[4],  *b1a = (const float*)d_in[5];
    const float *w2a = (const float*)d_in[6],  *b2a = (const float*)d_in[7];
    const float *ga0 = (const float*)d_in[8],  *be0 = (const float*)d_in[9];
    const float *w1b = (const float*)d_in[10], *b1b = (const float*)d_in[11];
    const float *w2b = (const float*)d_in[12], *b2b = (const float*)d_in[13];
    const float *ga1 = (const float*)d_in[14], *be1 = (const float*)d_in[15];
    const float *wf  = (const float*)d_in[16], *bfv = (const float*)d_in[17];
    const float *wf1 = (const float*)d_in[18], *bf1 = (const float*)d_in[19];
    const float *wf2 = (const float*)d_in[20], *bf2 = (const float*)d_in[21];
    float* out = (float*)d_out;

    float *u, *za, *h0, *z1, *h1, *p0, *p1;
    double* bnacc;
    cudaGetSymbolAddress((void**)&u,  g_u);
    cudaGetSymbolAddress((void**)&za, g_za);
    cudaGetSymbolAddress((void**)&h0, g_h0);
    cudaGetSymbolAddress((void**)&z1, g_z1);
    cudaGetSymbolAddress((void**)&h1, g_h1);
    cudaGetSymbolAddress((void**)&p0, g_p0);
    cudaGetSymbolAddress((void**)&p1, g_p1);
    cudaGetSymbolAddress((void**)&bnacc, g_bnacc);

    const int SMEM_PROJ = (128 * P128 + 128 * 64) * 4;
    const int SMEM_MLP2 = (128 * P64 + 64 * 64 + 2 * 64) * 4;
    const int SMEM_MLP  = (128 * P64 + 2 * 64 * 64 + 2 * 64) * 4;   // zs reused as ys
    const int SMEM_HEAD = (64 * P128 + 128 * 64 + 64 * 64 + 2 * 64 * P64 + 2 * 64 + 128 + 4) * 4;
    cudaFuncSetAttribute((void*)k_proj, cudaFuncAttributeMaxDynamicSharedMemorySize, SMEM_PROJ);
    cudaFuncSetAttribute((void*)k_mlp2, cudaFuncAttributeMaxDynamicSharedMemorySize, SMEM_MLP2);
    cudaFuncSetAttribute((void*)k_mlp,  cudaFuncAttributeMaxDynamicSharedMemorySize, SMEM_MLP);
    cudaFuncSetAttribute((void*)k_head, cudaFuncAttributeMaxDynamicSharedMemorySize, SMEM_HEAD);

    // dtype detection must precede any index consumer
    k_detect<<<1, 1>>>((const int*)ei);

    cudaMemsetAsync(bnacc, 0, sizeof(double) * 4 * DD, 0);
    cudaMemsetAsync(p0, 0, sizeof(float) * GG * DD, 0);
    cudaMemsetAsync(p1, 0, sizeof(float) * GG * DD, 0);

    const int NBLK128 = (NN + 127) / 128;
    const int SBLK    = (EE * 16 + 255) / 256;
    const int ABLK    = (NN * 16 + 255) / 256;

    // layer 0: project first (linearity), scatter in D=64 domain
    k_proj<<<NBLK128, 256, SMEM_PROJ>>>(x, w1a, u, za);
    k_scatter<<<SBLK, 256>>>(ei, ew, u, za);
    k_mlp2<<<NBLK128, 256, SMEM_MLP2>>>(za, b1a, w2a, b2a, h0, bnacc);
    k_bnapply<true><<<ABLK, 256>>>(h0, bnacc, ga0, be0, batch, z1, p0);

    // layer 1
    k_scatter<<<SBLK, 256>>>(ei, ew, h0, z1);
    k_mlp<<<NBLK128, 256, SMEM_MLP>>>(z1, w1b, b1b, w2b, b2b, h1, bnacc + 2 * DD);
    k_bnapply<false><<<ABLK, 256>>>(h1, bnacc + 2 * DD, ga1, be1, batch, nullptr, p1);

    // head
    k_head<<<GG / 64, 256, SMEM_HEAD>>>(p0, p1, wf, bfv, wf1, bf1, wf2, bf2, out);
}